// round 1
// baseline (speedup 1.0000x reference)
#include <cuda_runtime.h>
#include <math_constants.h>
#include <cstddef>

#define BATCH 32
#define C_IN  256
#define NPIX  1024
#define D8    32
#define KT    64

// Scratch for projections (device globals: allocation-free)
__device__ float g_q[BATCH * D8 * NPIX];    // [B, 32, N]
__device__ float g_k[BATCH * D8 * NPIX];    // [B, 32, N]
__device__ float g_v[BATCH * C_IN * NPIX];  // [B, 256, N]

// ---------------------------------------------------------------------------
// Projection GEMM: out[b,d,n] = sum_c W[d,c] * x[b,c,n] + bias[d]
// Block tile: 32 (d) x 64 (n), K-tiles of 32. 256 threads, 8 outputs/thread.
// ---------------------------------------------------------------------------
__global__ __launch_bounds__(256) void proj_kernel(
    const float* __restrict__ x, const float* __restrict__ W,
    const float* __restrict__ bias, float* __restrict__ out, int D)
{
    __shared__ float Ws[32 * 33];
    __shared__ __align__(16) float Xs[32 * 64];

    const int tid = threadIdx.x;
    const int b  = blockIdx.z;
    const int d0 = blockIdx.y * 32;
    const int n0 = blockIdx.x * 64;
    const int ty = tid >> 4;   // 0..15 -> 2 d-rows each
    const int tx = tid & 15;   // 0..15 -> 4 n-cols each

    const float* xb = x + (size_t)b * C_IN * NPIX;

    float acc[2][4];
    #pragma unroll
    for (int i = 0; i < 2; i++)
        #pragma unroll
        for (int j = 0; j < 4; j++) acc[i][j] = 0.f;

    for (int kt = 0; kt < C_IN; kt += 32) {
        #pragma unroll
        for (int i = tid; i < 32 * 32; i += 256) {
            int r = i >> 5, c = i & 31;
            Ws[r * 33 + c] = W[(size_t)(d0 + r) * C_IN + kt + c];
        }
        #pragma unroll
        for (int i = tid; i < 32 * 64; i += 256) {
            int r = i >> 6, c = i & 63;
            Xs[r * 64 + c] = xb[(size_t)(kt + r) * NPIX + n0 + c];
        }
        __syncthreads();

        #pragma unroll
        for (int k = 0; k < 32; k++) {
            float w0 = Ws[(ty * 2 + 0) * 33 + k];
            float w1 = Ws[(ty * 2 + 1) * 33 + k];
            float4 xv = *(const float4*)&Xs[k * 64 + tx * 4];
            acc[0][0] += w0 * xv.x; acc[0][1] += w0 * xv.y;
            acc[0][2] += w0 * xv.z; acc[0][3] += w0 * xv.w;
            acc[1][0] += w1 * xv.x; acc[1][1] += w1 * xv.y;
            acc[1][2] += w1 * xv.z; acc[1][3] += w1 * xv.w;
        }
        __syncthreads();
    }

    #pragma unroll
    for (int i = 0; i < 2; i++) {
        int d = d0 + ty * 2 + i;
        float bv = bias[d];
        float* orow = out + ((size_t)b * D + d) * NPIX + n0 + tx * 4;
        #pragma unroll
        for (int j = 0; j < 4; j++) orow[j] = acc[i][j] + bv;
    }
}

// ---------------------------------------------------------------------------
// Fused flash-style attention + epilogue (gamma*out + x).
// Block = (batch b, 32 query rows). 256 threads.
//   thread: query row n = tid/8; channel set c = cc*8 + g (g = tid%7..), cc<32
// Online softmax over 16 key tiles of 64.
// Dynamic SMEM layout (floats):
//   Qs[32][32], Ks[32][68], P[32][68], Vs[256][68]   = 91136 B
// ---------------------------------------------------------------------------
constexpr int QS_OFF = 0;
constexpr int KS_OFF = QS_OFF + 32 * 32;
constexpr int P_OFF  = KS_OFF + 32 * 68;
constexpr int VS_OFF = P_OFF + 32 * 68;
constexpr int SMEM_FLOATS = VS_OFF + 256 * 68;
constexpr int SMEM_BYTES  = SMEM_FLOATS * 4;   // 91136

__global__ __launch_bounds__(256, 2) void attn_kernel(
    const float* __restrict__ x, const float* __restrict__ gamma_p,
    float* __restrict__ out)
{
    extern __shared__ __align__(16) float sm[];

    const int tid = threadIdx.x;
    const int b  = blockIdx.y;
    const int nt = blockIdx.x * 32;
    const int n  = tid >> 3;   // query row 0..31
    const int g  = tid & 7;    // channel group 0..7

    const float* qb = g_q + (size_t)b * D8 * NPIX;
    const float* kb = g_k + (size_t)b * D8 * NPIX;
    const float* vb = g_v + (size_t)b * C_IN * NPIX;

    // Load Q tile: Qs[d][nn] = q[b,d,nt+nn]
    #pragma unroll
    for (int i = tid; i < D8 * 32; i += 256) {
        int d = i >> 5, nn = i & 31;
        sm[QS_OFF + d * 32 + nn] = qb[(size_t)d * NPIX + nt + nn];
    }

    float o[32];
    #pragma unroll
    for (int i = 0; i < 32; i++) o[i] = 0.f;
    float m_run = -CUDART_INF_F;
    float l_run = 0.f;

    for (int mt = 0; mt < NPIX; mt += KT) {
        __syncthreads();   // previous tile's P/Vs consumers done

        // K tile: Ks[r][m], 32 rows x 64 cols (float4 copies)
        #pragma unroll
        for (int i = tid; i < 32 * 16; i += 256) {
            int r = i >> 4, m4 = i & 15;
            ((float4*)&sm[KS_OFF + r * 68])[m4] =
                ((const float4*)&kb[(size_t)r * NPIX + mt])[m4];
        }
        // V tile: Vs[c][m], 256 rows x 64 cols
        #pragma unroll
        for (int i = tid; i < 256 * 16; i += 256) {
            int r = i >> 4, m4 = i & 15;
            ((float4*)&sm[VS_OFF + r * 68])[m4] =
                ((const float4*)&vb[(size_t)r * NPIX + mt])[m4];
        }
        __syncthreads();

        // Scores for this thread's 8 keys: m = g*8 + j
        float s[8];
        #pragma unroll
        for (int j = 0; j < 8; j++) s[j] = 0.f;
        #pragma unroll
        for (int d = 0; d < 32; d++) {
            float qv = sm[QS_OFF + d * 32 + n];
            const float* krow = &sm[KS_OFF + d * 68 + g * 8];
            #pragma unroll
            for (int j = 0; j < 8; j++) s[j] += qv * krow[j];
        }

        // Tile max over 64 keys (8 local + shfl over the 8-lane row group)
        float tmax = s[0];
        #pragma unroll
        for (int j = 1; j < 8; j++) tmax = fmaxf(tmax, s[j]);
        tmax = fmaxf(tmax, __shfl_xor_sync(0xffffffffu, tmax, 1));
        tmax = fmaxf(tmax, __shfl_xor_sync(0xffffffffu, tmax, 2));
        tmax = fmaxf(tmax, __shfl_xor_sync(0xffffffffu, tmax, 4));

        float new_m = fmaxf(m_run, tmax);
        float corr  = __expf(m_run - new_m);

        float tsum = 0.f;
        #pragma unroll
        for (int j = 0; j < 8; j++) {
            float p = __expf(s[j] - new_m);
            sm[P_OFF + n * 68 + g * 8 + j] = p;
            tsum += p;
        }
        tsum += __shfl_xor_sync(0xffffffffu, tsum, 1);
        tsum += __shfl_xor_sync(0xffffffffu, tsum, 2);
        tsum += __shfl_xor_sync(0xffffffffu, tsum, 4);

        l_run = l_run * corr + tsum;
        m_run = new_m;
        #pragma unroll
        for (int i = 0; i < 32; i++) o[i] *= corr;

        __syncthreads();   // P visible to all

        // AV: o[cc] += sum_m P[n][m] * Vs[cc*8+g][m]
        const float4* prow = (const float4*)&sm[P_OFF + n * 68];
        #pragma unroll 1
        for (int m4 = 0; m4 < 16; m4++) {
            float4 p4 = prow[m4];
            #pragma unroll
            for (int cc = 0; cc < 32; cc++) {
                int c = cc * 8 + g;
                float4 v4 = ((const float4*)&sm[VS_OFF + c * 68])[m4];
                o[cc] += p4.x * v4.x + p4.y * v4.y + p4.z * v4.z + p4.w * v4.w;
            }
        }
    }

    // Epilogue: stage (gamma/l)*o into SMEM, then coalesced gamma*out + x
    float inv = gamma_p[0] / l_run;
    __syncthreads();   // everyone done reading Vs
    #pragma unroll
    for (int cc = 0; cc < 32; cc++) {
        int c = cc * 8 + g;
        sm[VS_OFF + c * 68 + n] = o[cc] * inv;
    }
    __syncthreads();

    const float* xb = x   + (size_t)b * C_IN * NPIX + nt;
    float*       ob = out + (size_t)b * C_IN * NPIX + nt;
    #pragma unroll
    for (int i = tid; i < C_IN * 32; i += 256) {
        int c = i >> 5, nn = i & 31;
        ob[(size_t)c * NPIX + nn] = sm[VS_OFF + c * 68 + nn] + xb[(size_t)c * NPIX + nn];
    }
}

// ---------------------------------------------------------------------------
extern "C" void kernel_launch(void* const* d_in, const int* in_sizes, int n_in,
                              void* d_out, int out_size)
{
    const float* x     = (const float*)d_in[0];
    const float* Wq    = (const float*)d_in[1];
    const float* bq    = (const float*)d_in[2];
    const float* Wk    = (const float*)d_in[3];
    const float* bk    = (const float*)d_in[4];
    const float* Wv    = (const float*)d_in[5];
    const float* bv    = (const float*)d_in[6];
    const float* gamma = (const float*)d_in[7];
    float* out = (float*)d_out;

    float *q, *k, *v;
    cudaGetSymbolAddress((void**)&q, g_q);
    cudaGetSymbolAddress((void**)&k, g_k);
    cudaGetSymbolAddress((void**)&v, g_v);

    static bool attr_set = false;
    if (!attr_set) {
        cudaFuncSetAttribute(attn_kernel,
                             cudaFuncAttributeMaxDynamicSharedMemorySize,
                             SMEM_BYTES);
        attr_set = true;
    }

    proj_kernel<<<dim3(NPIX / 64, 1, BATCH), 256>>>(x, Wq, bq, q, D8);
    proj_kernel<<<dim3(NPIX / 64, 1, BATCH), 256>>>(x, Wk, bk, k, D8);
    proj_kernel<<<dim3(NPIX / 64, C_IN / 32, BATCH), 256>>>(x, Wv, bv, v, C_IN);
    attn_kernel<<<dim3(NPIX / 32, BATCH), 256, SMEM_BYTES>>>(x, gamma, out);
}

// round 2
// speedup vs baseline: 1.6698x; 1.6698x over previous
#include <cuda_runtime.h>
#include <math_constants.h>
#include <cstddef>

#define BATCH 32
#define C_IN  256
#define NPIX  1024
#define D8    32
#define KT    64

// Scratch for projections (device globals: allocation-free)
__device__ float g_q[BATCH * D8 * NPIX];    // [B, 32, N]
__device__ float g_k[BATCH * D8 * NPIX];    // [B, 32, N]
__device__ float g_v[BATCH * C_IN * NPIX];  // [B, 256, N]

// ---------------------------------------------------------------------------
// Packed f32x2 helpers (Blackwell 2x-rate fp32)
// ---------------------------------------------------------------------------
typedef unsigned long long u64t;

__device__ __forceinline__ u64t pack2(float lo, float hi) {
    u64t r;
    asm("mov.b64 %0, {%1, %2};"
        : "=l"(r) : "r"(__float_as_uint(lo)), "r"(__float_as_uint(hi)));
    return r;
}
__device__ __forceinline__ void fma2(u64t& d, u64t a, u64t b) {
    asm("fma.rn.f32x2 %0, %1, %2, %0;" : "+l"(d) : "l"(a), "l"(b));
}
__device__ __forceinline__ void mul2(u64t& d, u64t a) {
    asm("mul.rn.f32x2 %0, %0, %1;" : "+l"(d) : "l"(a));
}
__device__ __forceinline__ float2 unpack2(u64t v) {
    unsigned lo, hi;
    asm("mov.b64 {%0, %1}, %2;" : "=r"(lo), "=r"(hi) : "l"(v));
    return make_float2(__uint_as_float(lo), __uint_as_float(hi));
}

// ---------------------------------------------------------------------------
// Projection GEMM: out[b,d,n] = sum_c W[d,c] * x[b,c,n] + bias[d]
// Block tile: 32 (d) x 64 (n), K-tiles of 32. 256 threads, 8 outputs/thread.
// f32x2-packed over output columns (free packing from float4 X loads).
// ---------------------------------------------------------------------------
__global__ __launch_bounds__(256) void proj_kernel(
    const float* __restrict__ x, const float* __restrict__ W,
    const float* __restrict__ bias, float* __restrict__ out, int D)
{
    __shared__ float Ws[32 * 33];
    __shared__ __align__(16) float Xs[32 * 64];

    const int tid = threadIdx.x;
    const int b  = blockIdx.z;
    const int d0 = blockIdx.y * 32;
    const int n0 = blockIdx.x * 64;
    const int ty = tid >> 4;   // 0..15 -> 2 d-rows each
    const int tx = tid & 15;   // 0..15 -> 4 n-cols each

    const float* xb = x + (size_t)b * C_IN * NPIX;

    u64t acc2[2][2];
    acc2[0][0] = acc2[0][1] = acc2[1][0] = acc2[1][1] = 0ull;

    for (int kt = 0; kt < C_IN; kt += 32) {
        #pragma unroll
        for (int i = tid; i < 32 * 32; i += 256) {
            int r = i >> 5, c = i & 31;
            Ws[r * 33 + c] = W[(size_t)(d0 + r) * C_IN + kt + c];
        }
        #pragma unroll
        for (int i = tid; i < 32 * 64; i += 256) {
            int r = i >> 6, c = i & 63;
            Xs[r * 64 + c] = xb[(size_t)(kt + r) * NPIX + n0 + c];
        }
        __syncthreads();

        #pragma unroll 8
        for (int k = 0; k < 32; k++) {
            float w0 = Ws[(ty * 2 + 0) * 33 + k];
            float w1 = Ws[(ty * 2 + 1) * 33 + k];
            u64t w02 = pack2(w0, w0);
            u64t w12 = pack2(w1, w1);
            ulonglong2 xv = *(const ulonglong2*)&Xs[k * 64 + tx * 4];
            fma2(acc2[0][0], w02, xv.x); fma2(acc2[0][1], w02, xv.y);
            fma2(acc2[1][0], w12, xv.x); fma2(acc2[1][1], w12, xv.y);
        }
        __syncthreads();
    }

    #pragma unroll
    for (int i = 0; i < 2; i++) {
        int d = d0 + ty * 2 + i;
        float bv = bias[d];
        float2 a = unpack2(acc2[i][0]);
        float2 c = unpack2(acc2[i][1]);
        float4 o4 = make_float4(a.x + bv, a.y + bv, c.x + bv, c.y + bv);
        *(float4*)(out + ((size_t)b * D + d) * NPIX + n0 + tx * 4) = o4;
    }
}

// ---------------------------------------------------------------------------
// Fused flash-style attention + epilogue (gamma*out + x).
// Block = (batch b, 32 query rows). 256 threads.
// QK/softmax mapping : n = tid>>3 (row), g = tid&7 (8 keys each)
// AV mapping         : rg = tid>>5 (4 rows), cg = tid&31, channels c=j*32+cg
// f32x2 packs the key dimension (even/odd partial sums, summed at the end).
// Dynamic SMEM (floats): Qs[32][32] Ks[32][68] P[32][68] Vs[256][68] corr/l[64]
// ---------------------------------------------------------------------------
constexpr int QS_OFF = 0;
constexpr int KS_OFF = QS_OFF + 32 * 32;
constexpr int P_OFF  = KS_OFF + 32 * 68;
constexpr int VS_OFF = P_OFF + 32 * 68;
constexpr int SCORR_OFF = VS_OFF + 256 * 68;
constexpr int SL_OFF    = SCORR_OFF + 32;
constexpr int SMEM_FLOATS = SL_OFF + 32;
constexpr int SMEM_BYTES  = SMEM_FLOATS * 4;   // 91392 B

__global__ __launch_bounds__(256, 2) void attn_kernel(
    const float* __restrict__ x, const float* __restrict__ gamma_p,
    float* __restrict__ out)
{
    extern __shared__ __align__(16) float sm[];

    const int tid = threadIdx.x;
    const int b  = blockIdx.y;
    const int nt = blockIdx.x * 32;
    const int n  = tid >> 3;   // QK: query row 0..31
    const int g  = tid & 7;    // QK: key group 0..7
    const int rg = tid >> 5;   // AV: row group (4 rows)
    const int cg = tid & 31;   // AV: channel lane
    const int r0 = rg * 4;

    const float* qb = g_q + (size_t)b * D8 * NPIX;
    const float* kb = g_k + (size_t)b * D8 * NPIX;
    const float* vb = g_v + (size_t)b * C_IN * NPIX;

    // Load Q tile: Qs[d][nn] = q[b,d,nt+nn]
    #pragma unroll
    for (int i = tid; i < D8 * 32; i += 256) {
        int d = i >> 5, nn = i & 31;
        sm[QS_OFF + d * 32 + nn] = qb[(size_t)d * NPIX + nt + nn];
    }

    u64t acc2[4][8];
    #pragma unroll
    for (int i = 0; i < 4; i++)
        #pragma unroll
        for (int j = 0; j < 8; j++) acc2[i][j] = 0ull;

    float m_run = -CUDART_INF_F;
    float l_run = 0.f;

    for (int mt = 0; mt < NPIX; mt += KT) {
        __syncthreads();   // previous tile's P/Vs/corr consumers done

        // K tile: Ks[r][m], 32 x 64 (float4 copies)
        #pragma unroll
        for (int i = tid; i < 32 * 16; i += 256) {
            int r = i >> 4, m4 = i & 15;
            ((float4*)&sm[KS_OFF + r * 68])[m4] =
                ((const float4*)&kb[(size_t)r * NPIX + mt])[m4];
        }
        // V tile: Vs[c][m], 256 x 64
        #pragma unroll
        for (int i = tid; i < 256 * 16; i += 256) {
            int r = i >> 4, m4 = i & 15;
            ((float4*)&sm[VS_OFF + r * 68])[m4] =
                ((const float4*)&vb[(size_t)r * NPIX + mt])[m4];
        }
        __syncthreads();

        // ---- QK: scores for keys m = g*8 + {0..7}, packed pairs over m ----
        u64t s2[4] = {0ull, 0ull, 0ull, 0ull};
        #pragma unroll 8
        for (int d = 0; d < 32; d++) {
            float qv = sm[QS_OFF + d * 32 + n];
            u64t q2 = pack2(qv, qv);
            const ulonglong2* kp = (const ulonglong2*)&sm[KS_OFF + d * 68 + g * 8];
            ulonglong2 ka = kp[0];
            ulonglong2 kc = kp[1];
            fma2(s2[0], q2, ka.x); fma2(s2[1], q2, ka.y);
            fma2(s2[2], q2, kc.x); fma2(s2[3], q2, kc.y);
        }
        float s[8];
        #pragma unroll
        for (int j = 0; j < 4; j++) {
            float2 f = unpack2(s2[j]);
            s[2 * j] = f.x; s[2 * j + 1] = f.y;
        }

        // Tile max over 64 keys (8 local + shfl over 8-lane row group)
        float tmax = s[0];
        #pragma unroll
        for (int j = 1; j < 8; j++) tmax = fmaxf(tmax, s[j]);
        tmax = fmaxf(tmax, __shfl_xor_sync(0xffffffffu, tmax, 1));
        tmax = fmaxf(tmax, __shfl_xor_sync(0xffffffffu, tmax, 2));
        tmax = fmaxf(tmax, __shfl_xor_sync(0xffffffffu, tmax, 4));

        float new_m = fmaxf(m_run, tmax);
        float corr  = __expf(m_run - new_m);

        float p[8];
        float tsum = 0.f;
        #pragma unroll
        for (int j = 0; j < 8; j++) {
            p[j] = __expf(s[j] - new_m);
            tsum += p[j];
        }
        *(float4*)&sm[P_OFF + n * 68 + g * 8]     = make_float4(p[0], p[1], p[2], p[3]);
        *(float4*)&sm[P_OFF + n * 68 + g * 8 + 4] = make_float4(p[4], p[5], p[6], p[7]);

        tsum += __shfl_xor_sync(0xffffffffu, tsum, 1);
        tsum += __shfl_xor_sync(0xffffffffu, tsum, 2);
        tsum += __shfl_xor_sync(0xffffffffu, tsum, 4);

        l_run = l_run * corr + tsum;
        m_run = new_m;

        if (g == 0) {
            sm[SCORR_OFF + n] = corr;
            if (mt == NPIX - KT) sm[SL_OFF + n] = l_run;
        }
        __syncthreads();   // P + corr (+l) visible

        // ---- rescale accumulators by per-row corr ----
        #pragma unroll
        for (int i = 0; i < 4; i++) {
            float cf = sm[SCORR_OFF + r0 + i];
            u64t c2 = pack2(cf, cf);
            #pragma unroll
            for (int j = 0; j < 8; j++) mul2(acc2[i][j], c2);
        }

        // ---- AV: acc2[i][j] += P[r0+i][m] * Vs[j*32+cg][m] over this tile ----
        #pragma unroll 2
        for (int m4 = 0; m4 < 16; m4++) {
            ulonglong2 p0 = *(const ulonglong2*)&sm[P_OFF + (r0 + 0) * 68 + m4 * 4];
            ulonglong2 p1 = *(const ulonglong2*)&sm[P_OFF + (r0 + 1) * 68 + m4 * 4];
            ulonglong2 p2 = *(const ulonglong2*)&sm[P_OFF + (r0 + 2) * 68 + m4 * 4];
            ulonglong2 p3 = *(const ulonglong2*)&sm[P_OFF + (r0 + 3) * 68 + m4 * 4];
            #pragma unroll
            for (int j = 0; j < 8; j++) {
                ulonglong2 vv =
                    *(const ulonglong2*)&sm[VS_OFF + (j * 32 + cg) * 68 + m4 * 4];
                fma2(acc2[0][j], p0.x, vv.x); fma2(acc2[0][j], p0.y, vv.y);
                fma2(acc2[1][j], p1.x, vv.x); fma2(acc2[1][j], p1.y, vv.y);
                fma2(acc2[2][j], p2.x, vv.x); fma2(acc2[2][j], p2.y, vv.y);
                fma2(acc2[3][j], p3.x, vv.x); fma2(acc2[3][j], p3.y, vv.y);
            }
        }
    }

    // ---- epilogue: stage (gamma/l)*o into Vs, then coalesced out = . + x ----
    float gma = gamma_p[0];
    __syncthreads();   // all AV reads of Vs done
    #pragma unroll
    for (int i = 0; i < 4; i++) {
        float inv = gma / sm[SL_OFF + r0 + i];
        #pragma unroll
        for (int j = 0; j < 8; j++) {
            float2 f = unpack2(acc2[i][j]);
            sm[VS_OFF + (j * 32 + cg) * 68 + (r0 + i)] = (f.x + f.y) * inv;
        }
    }
    __syncthreads();

    const float* xb = x   + (size_t)b * C_IN * NPIX + nt;
    float*       ob = out + (size_t)b * C_IN * NPIX + nt;
    #pragma unroll
    for (int i = tid; i < C_IN * 32; i += 256) {
        int c = i >> 5, nn = i & 31;
        ob[(size_t)c * NPIX + nn] = sm[VS_OFF + c * 68 + nn] + xb[(size_t)c * NPIX + nn];
    }
}

// ---------------------------------------------------------------------------
extern "C" void kernel_launch(void* const* d_in, const int* in_sizes, int n_in,
                              void* d_out, int out_size)
{
    const float* x     = (const float*)d_in[0];
    const float* Wq    = (const float*)d_in[1];
    const float* bq    = (const float*)d_in[2];
    const float* Wk    = (const float*)d_in[3];
    const float* bk    = (const float*)d_in[4];
    const float* Wv    = (const float*)d_in[5];
    const float* bv    = (const float*)d_in[6];
    const float* gamma = (const float*)d_in[7];
    float* out = (float*)d_out;

    float *q, *k, *v;
    cudaGetSymbolAddress((void**)&q, g_q);
    cudaGetSymbolAddress((void**)&k, g_k);
    cudaGetSymbolAddress((void**)&v, g_v);

    static bool attr_set = false;
    if (!attr_set) {
        cudaFuncSetAttribute(attn_kernel,
                             cudaFuncAttributeMaxDynamicSharedMemorySize,
                             SMEM_BYTES);
        attr_set = true;
    }

    proj_kernel<<<dim3(NPIX / 64, 1, BATCH), 256>>>(x, Wq, bq, q, D8);
    proj_kernel<<<dim3(NPIX / 64, 1, BATCH), 256>>>(x, Wk, bk, k, D8);
    proj_kernel<<<dim3(NPIX / 64, C_IN / 32, BATCH), 256>>>(x, Wv, bv, v, C_IN);
    attn_kernel<<<dim3(NPIX / 32, BATCH), 256, SMEM_BYTES>>>(x, gamma, out);
}

// round 6
// speedup vs baseline: 3.8605x; 2.3120x over previous
#include <cuda_runtime.h>
#include <cstdint>
#include <cstddef>

#define BATCH 32
#define C_IN  256
#define NPIX  1024
#define D8    32
#define KT    64
#define NTILES 16
#define MROWS 128

// Scratch for projections (device globals: allocation-free)
__device__ float g_qt[BATCH * NPIX * D8];    // [b][n][32]  q, tf32-rounded
__device__ float g_kt[BATCH * NPIX * D8];    // [b][n][32]  k, tf32-rounded
__device__ float g_v [BATCH * C_IN * NPIX];  // [b][c][n]   v, tf32-rounded

// ---------------------------------------------------------------------------
// helpers
// ---------------------------------------------------------------------------
typedef unsigned long long u64t;
__device__ __forceinline__ u64t pack2(float lo, float hi) {
    u64t r;
    asm("mov.b64 %0, {%1, %2};"
        : "=l"(r) : "r"(__float_as_uint(lo)), "r"(__float_as_uint(hi)));
    return r;
}
__device__ __forceinline__ void fma2(u64t& d, u64t a, u64t b) {
    asm("fma.rn.f32x2 %0, %1, %2, %0;" : "+l"(d) : "l"(a), "l"(b));
}
__device__ __forceinline__ float2 unpack2(u64t v) {
    unsigned lo, hi;
    asm("mov.b64 {%0, %1}, %2;" : "=r"(lo), "=r"(hi) : "l"(v));
    return make_float2(__uint_as_float(lo), __uint_as_float(hi));
}
__device__ __forceinline__ float to_tf32(float f) {
    uint32_t u;
    asm("cvt.rna.tf32.f32 %0, %1;" : "=r"(u) : "f"(f));
    return __uint_as_float(u);
}
__device__ __forceinline__ uint32_t smem_u32(const void* p) {
    uint32_t a;
    asm("{ .reg .u64 t; cvta.to.shared.u64 t, %1; cvt.u32.u64 %0, t; }"
        : "=r"(a) : "l"(p));
    return a;
}
// mma.sync m16n8k8 tf32 (baseline sm_80+ PTX, works on plain sm_103 target)
__device__ __forceinline__ void mma16n8k8(float* d, const float* a, const float* b) {
    asm volatile("mma.sync.aligned.m16n8k8.row.col.f32.tf32.tf32.f32 "
        "{%0,%1,%2,%3}, {%4,%5,%6,%7}, {%8,%9}, {%0,%1,%2,%3};"
        : "+f"(d[0]), "+f"(d[1]), "+f"(d[2]), "+f"(d[3])
        : "r"(__float_as_uint(a[0])), "r"(__float_as_uint(a[1])),
          "r"(__float_as_uint(a[2])), "r"(__float_as_uint(a[3])),
          "r"(__float_as_uint(b[0])), "r"(__float_as_uint(b[1])));
}
__device__ __forceinline__ void cp16(uint32_t dst, const void* src) {
    asm volatile("cp.async.cg.shared.global [%0], [%1], 16;" :: "r"(dst), "l"(src));
}
#define CP_COMMIT() asm volatile("cp.async.commit_group;" ::: "memory")
#define CP_WAIT1()  asm volatile("cp.async.wait_group 1;" ::: "memory")
#define CP_WAIT0()  asm volatile("cp.async.wait_group 0;" ::: "memory")

// ---------------------------------------------------------------------------
// Projection GEMM (V): out[b,d,n] = sum_c W[d,c] x[b,c,n] + bias[d]
// ---------------------------------------------------------------------------
__global__ __launch_bounds__(256) void proj_kernel(
    const float* __restrict__ x, const float* __restrict__ W,
    const float* __restrict__ bias, float* __restrict__ out, int D)
{
    __shared__ float Ws[32 * 33];
    __shared__ __align__(16) float Xs[32 * 64];

    const int tid = threadIdx.x;
    const int b  = blockIdx.z;
    const int d0 = blockIdx.y * 32;
    const int n0 = blockIdx.x * 64;
    const int ty = tid >> 4, tx = tid & 15;
    const float* xb = x + (size_t)b * C_IN * NPIX;

    u64t acc2[2][2] = {{0ull, 0ull}, {0ull, 0ull}};

    for (int kt = 0; kt < C_IN; kt += 32) {
        #pragma unroll
        for (int i = tid; i < 32 * 32; i += 256) {
            int r = i >> 5, c = i & 31;
            Ws[r * 33 + c] = W[(size_t)(d0 + r) * C_IN + kt + c];
        }
        #pragma unroll
        for (int i = tid; i < 32 * 64; i += 256) {
            int r = i >> 6, c = i & 63;
            Xs[r * 64 + c] = xb[(size_t)(kt + r) * NPIX + n0 + c];
        }
        __syncthreads();
        #pragma unroll 8
        for (int k = 0; k < 32; k++) {
            float w0 = Ws[(ty * 2 + 0) * 33 + k];
            float w1 = Ws[(ty * 2 + 1) * 33 + k];
            u64t w02 = pack2(w0, w0), w12 = pack2(w1, w1);
            ulonglong2 xv = *(const ulonglong2*)&Xs[k * 64 + tx * 4];
            fma2(acc2[0][0], w02, xv.x); fma2(acc2[0][1], w02, xv.y);
            fma2(acc2[1][0], w12, xv.x); fma2(acc2[1][1], w12, xv.y);
        }
        __syncthreads();
    }
    #pragma unroll
    for (int i = 0; i < 2; i++) {
        int d = d0 + ty * 2 + i;
        float bv = bias[d];
        float2 a = unpack2(acc2[i][0]), c = unpack2(acc2[i][1]);
        float4 o4 = make_float4(to_tf32(a.x + bv), to_tf32(a.y + bv),
                                to_tf32(c.x + bv), to_tf32(c.y + bv));
        *(float4*)(out + ((size_t)b * D + d) * NPIX + n0 + tx * 4) = o4;
    }
}

// ---------------------------------------------------------------------------
// Projection for q/k with transposed store: out[b][n][32], tf32-rounded
// ---------------------------------------------------------------------------
__global__ __launch_bounds__(256) void proj_qk_kernel(
    const float* __restrict__ x, const float* __restrict__ W,
    const float* __restrict__ bias, float* __restrict__ out)
{
    __shared__ float Ws[32 * 33];
    __shared__ __align__(16) float Xs[32 * 64];

    const int tid = threadIdx.x;
    const int b  = blockIdx.z;
    const int n0 = blockIdx.x * 64;
    const int ty = tid >> 4, tx = tid & 15;
    const float* xb = x + (size_t)b * C_IN * NPIX;

    u64t acc2[2][2] = {{0ull, 0ull}, {0ull, 0ull}};

    for (int kt = 0; kt < C_IN; kt += 32) {
        #pragma unroll
        for (int i = tid; i < 32 * 32; i += 256) {
            int r = i >> 5, c = i & 31;
            Ws[r * 33 + c] = W[(size_t)r * C_IN + kt + c];
        }
        #pragma unroll
        for (int i = tid; i < 32 * 64; i += 256) {
            int r = i >> 6, c = i & 63;
            Xs[r * 64 + c] = xb[(size_t)(kt + r) * NPIX + n0 + c];
        }
        __syncthreads();
        #pragma unroll 8
        for (int k = 0; k < 32; k++) {
            float w0 = Ws[(ty * 2 + 0) * 33 + k];
            float w1 = Ws[(ty * 2 + 1) * 33 + k];
            u64t w02 = pack2(w0, w0), w12 = pack2(w1, w1);
            ulonglong2 xv = *(const ulonglong2*)&Xs[k * 64 + tx * 4];
            fma2(acc2[0][0], w02, xv.x); fma2(acc2[0][1], w02, xv.y);
            fma2(acc2[1][0], w12, xv.x); fma2(acc2[1][1], w12, xv.y);
        }
        __syncthreads();
    }
    #pragma unroll
    for (int i = 0; i < 2; i++) {
        int d = ty * 2 + i;
        float bv = bias[d];
        float2 a = unpack2(acc2[i][0]), c = unpack2(acc2[i][1]);
        float vals[4] = {to_tf32(a.x + bv), to_tf32(a.y + bv),
                         to_tf32(c.x + bv), to_tf32(c.y + bv)};
        #pragma unroll
        for (int j = 0; j < 4; j++)
            out[((size_t)b * NPIX + n0 + tx * 4 + j) * D8 + d] = vals[j];
    }
}

// ---------------------------------------------------------------------------
// mma.sync tf32 flash attention.
// CTA = (batch, 128 query rows), 256 threads = 8 warps.
// warp -> row-group rg = wid>>1 (32 rows = 2 m16), channel half ch0 = (wid&1)*128.
// Per 64-key tile: S = Q K^T (mma) -> exp -> P as A-fragments (shuffles) ->
// O += P V^T (mma). No max subtraction; normalize once at the end.
// SMEM (floats): Qs[128][36] | Ks[2][64][36] | Vs[2][256][68]  = 176128 B
// ---------------------------------------------------------------------------
constexpr int QS_F = 0;
constexpr int KS_F = 128 * 36;                 // 4608
constexpr int VS_F = KS_F + 2 * 64 * 36;       // 9216
constexpr int SMEM_ATTN = (VS_F + 2 * 256 * 68) * 4;   // 176128

__global__ void __launch_bounds__(256, 1) attn_mma_kernel(
    const float* __restrict__ x, const float* __restrict__ gamma_p,
    float* __restrict__ out)
{
    extern __shared__ __align__(16) float sm[];
    const int tid  = threadIdx.x;
    const int lane = tid & 31, wid = tid >> 5;
    const int b   = blockIdx.y;
    const int nt  = blockIdx.x * MROWS;
    const int m0  = (wid >> 1) * 32;
    const int ch0 = (wid & 1) * 128;
    const int g = lane >> 2, t = lane & 3;

    const float* qt = g_qt + (size_t)b * NPIX * D8;
    const float* kq = g_kt + (size_t)b * NPIX * D8;
    const float* vb = g_v  + (size_t)b * C_IN * NPIX;

    const uint32_t sb = smem_u32(sm);

    // Q tile -> smem [128][36]
    #pragma unroll
    for (int i = tid; i < 1024; i += 256) {
        int r = i >> 3, cg = i & 7;
        *(float4*)&sm[QS_F + r * 36 + cg * 4] =
            *(const float4*)&qt[(size_t)(nt + r) * D8 + cg * 4];
    }

    // Prefetch key-tiles 0 and 1 (cp.async, one commit group each)
    #pragma unroll
    for (int pb = 0; pb < 2; pb++) {
        const int mt = pb * KT;
        #pragma unroll
        for (int i = tid; i < 512; i += 256) {
            int r = i >> 3, cg = i & 7;
            cp16(sb + (uint32_t)(KS_F + pb * 2304 + r * 36 + cg * 4) * 4,
                 kq + (size_t)(mt + r) * D8 + cg * 4);
        }
        #pragma unroll
        for (int i = tid; i < 4096; i += 256) {
            int c = i >> 4, m4 = i & 15;
            cp16(sb + (uint32_t)(VS_F + pb * 17408 + c * 68 + m4 * 4) * 4,
                 vb + (size_t)c * NPIX + mt + m4 * 4);
        }
        CP_COMMIT();
    }

    float o[2][16][4];
    #pragma unroll
    for (int i = 0; i < 2; i++)
        #pragma unroll
        for (int j = 0; j < 16; j++)
            #pragma unroll
            for (int k = 0; k < 4; k++) o[i][j][k] = 0.f;

    float lsum[2][2] = {{0.f, 0.f}, {0.f, 0.f}};
    const int srcA = g * 4 + (t >> 1);
    const int srcB = srcA + 2;
    const bool odd = (t & 1) != 0;

    #pragma unroll 1
    for (int tt = 0; tt < NTILES; tt++) {
        const int buf = tt & 1;
        if (tt < NTILES - 1) { CP_WAIT1(); } else { CP_WAIT0(); }
        __syncthreads();

        const float* Ks = sm + KS_F + buf * 2304;
        const float* Vs = sm + VS_F + buf * 17408;

        // ---- QK: S[32 rows][64 keys] per warp ----
        float s[2][8][4];
        #pragma unroll
        for (int i = 0; i < 2; i++)
            #pragma unroll
            for (int j = 0; j < 8; j++)
                #pragma unroll
                for (int k = 0; k < 4; k++) s[i][j][k] = 0.f;

        #pragma unroll
        for (int sk = 0; sk < 4; sk++) {
            const int dd = sk * 8 + t;
            float a0[4], a1[4];
            a0[0] = sm[QS_F + (m0 + g) * 36 + dd];
            a0[1] = sm[QS_F + (m0 + g + 8) * 36 + dd];
            a0[2] = sm[QS_F + (m0 + g) * 36 + dd + 4];
            a0[3] = sm[QS_F + (m0 + g + 8) * 36 + dd + 4];
            a1[0] = sm[QS_F + (m0 + 16 + g) * 36 + dd];
            a1[1] = sm[QS_F + (m0 + 24 + g) * 36 + dd];
            a1[2] = sm[QS_F + (m0 + 16 + g) * 36 + dd + 4];
            a1[3] = sm[QS_F + (m0 + 24 + g) * 36 + dd + 4];
            #pragma unroll
            for (int n8 = 0; n8 < 8; n8++) {
                float bb[2];
                bb[0] = Ks[(n8 * 8 + g) * 36 + dd];
                bb[1] = Ks[(n8 * 8 + g) * 36 + dd + 4];
                mma16n8k8(s[0][n8], a0, bb);
                mma16n8k8(s[1][n8], a1, bb);
            }
        }

        // ---- softmax numerator + C-frag -> A-frag conversion (in regs) ----
        #pragma unroll
        for (int mt = 0; mt < 2; mt++) {
            #pragma unroll
            for (int k8 = 0; k8 < 8; k8++) {
                float p0 = to_tf32(__expf(s[mt][k8][0]));
                float p1 = to_tf32(__expf(s[mt][k8][1]));
                float p2 = to_tf32(__expf(s[mt][k8][2]));
                float p3 = to_tf32(__expf(s[mt][k8][3]));
                lsum[mt][0] += p0 + p1;
                lsum[mt][1] += p2 + p3;
                float u0 = __shfl_sync(0xffffffffu, p0, srcA);
                float u1 = __shfl_sync(0xffffffffu, p1, srcA);
                float u2 = __shfl_sync(0xffffffffu, p2, srcA);
                float u3 = __shfl_sync(0xffffffffu, p3, srcA);
                float w0 = __shfl_sync(0xffffffffu, p0, srcB);
                float w1 = __shfl_sync(0xffffffffu, p1, srcB);
                float w2 = __shfl_sync(0xffffffffu, p2, srcB);
                float w3 = __shfl_sync(0xffffffffu, p3, srcB);
                s[mt][k8][0] = odd ? u1 : u0;   // A[g][t]
                s[mt][k8][1] = odd ? u3 : u2;   // A[g+8][t]
                s[mt][k8][2] = odd ? w1 : w0;   // A[g][t+4]
                s[mt][k8][3] = odd ? w3 : w2;   // A[g+8][t+4]
            }
        }

        // ---- AV: O[32 rows][128 ch] += P V^T ----
        #pragma unroll
        for (int k8 = 0; k8 < 8; k8++) {
            #pragma unroll
            for (int n8 = 0; n8 < 16; n8++) {
                float bb[2];
                const int c = ch0 + n8 * 8 + g;
                bb[0] = Vs[c * 68 + k8 * 8 + t];
                bb[1] = Vs[c * 68 + k8 * 8 + t + 4];
                mma16n8k8(o[0][n8], s[0][k8], bb);
                mma16n8k8(o[1][n8], s[1][k8], bb);
            }
        }

        __syncthreads();   // all warps done reading buf before refilling it

        if (tt + 2 < NTILES) {
            const int mt = (tt + 2) * KT;
            #pragma unroll
            for (int i = tid; i < 512; i += 256) {
                int r = i >> 3, cg = i & 7;
                cp16(sb + (uint32_t)(KS_F + buf * 2304 + r * 36 + cg * 4) * 4,
                     kq + (size_t)(mt + r) * D8 + cg * 4);
            }
            #pragma unroll
            for (int i = tid; i < 4096; i += 256) {
                int c = i >> 4, m4 = i & 15;
                cp16(sb + (uint32_t)(VS_F + buf * 17408 + c * 68 + m4 * 4) * 4,
                     vb + (size_t)c * NPIX + mt + m4 * 4);
            }
            CP_COMMIT();
        }
    }

    // ---- epilogue: out = gamma * O / l + x ----
    #pragma unroll
    for (int mt = 0; mt < 2; mt++)
        #pragma unroll
        for (int h = 0; h < 2; h++) {
            lsum[mt][h] += __shfl_xor_sync(0xffffffffu, lsum[mt][h], 1);
            lsum[mt][h] += __shfl_xor_sync(0xffffffffu, lsum[mt][h], 2);
        }
    const float gma = gamma_p[0];
    float inv[2][2];
    #pragma unroll
    for (int mt = 0; mt < 2; mt++)
        #pragma unroll
        for (int h = 0; h < 2; h++) inv[mt][h] = gma / lsum[mt][h];

    #pragma unroll
    for (int mt = 0; mt < 2; mt++) {
        const int rbase = nt + m0 + mt * 16 + g;
        #pragma unroll
        for (int n8 = 0; n8 < 16; n8++) {
            const int c0 = ch0 + n8 * 8 + 2 * t;
            size_t gi = ((size_t)b * C_IN + c0) * NPIX + rbase;
            out[gi]            = o[mt][n8][0] * inv[mt][0] + x[gi];
            out[gi + NPIX]     = o[mt][n8][1] * inv[mt][0] + x[gi + NPIX];
            out[gi + 8]        = o[mt][n8][2] * inv[mt][1] + x[gi + 8];
            out[gi + NPIX + 8] = o[mt][n8][3] * inv[mt][1] + x[gi + NPIX + 8];
        }
    }
}

// ---------------------------------------------------------------------------
extern "C" void kernel_launch(void* const* d_in, const int* in_sizes, int n_in,
                              void* d_out, int out_size)
{
    const float* x     = (const float*)d_in[0];
    const float* Wq    = (const float*)d_in[1];
    const float* bq    = (const float*)d_in[2];
    const float* Wk    = (const float*)d_in[3];
    const float* bk    = (const float*)d_in[4];
    const float* Wv    = (const float*)d_in[5];
    const float* bv    = (const float*)d_in[6];
    const float* gamma = (const float*)d_in[7];
    float* out = (float*)d_out;

    float *qt, *ktp, *v;
    cudaGetSymbolAddress((void**)&qt,  g_qt);
    cudaGetSymbolAddress((void**)&ktp, g_kt);
    cudaGetSymbolAddress((void**)&v,   g_v);

    static bool attr_set = false;
    if (!attr_set) {
        cudaFuncSetAttribute(attn_mma_kernel,
                             cudaFuncAttributeMaxDynamicSharedMemorySize,
                             SMEM_ATTN);
        attr_set = true;
    }

    proj_qk_kernel<<<dim3(NPIX / 64, 1, BATCH), 256>>>(x, Wq, bq, qt);
    proj_qk_kernel<<<dim3(NPIX / 64, 1, BATCH), 256>>>(x, Wk, bk, ktp);
    proj_kernel<<<dim3(NPIX / 64, C_IN / 32, BATCH), 256>>>(x, Wv, bv, v, C_IN);
    attn_mma_kernel<<<dim3(NPIX / MROWS, BATCH), 256, SMEM_ATTN>>>(x, gamma, out);
}

// round 7
// speedup vs baseline: 7.9504x; 2.0594x over previous
#include <cuda_runtime.h>
#include <cstdint>
#include <cstddef>

#define BATCH 32
#define C_IN  256
#define NPIX  1024
#define D8    32
#define KT    64
#define NTILES 16
#define MROWS 128

// Scratch (device globals: allocation-free)
__device__ float g_qt[BATCH * NPIX * D8];    // [b][n][32]  q (tf32)
__device__ float g_kt[BATCH * NPIX * D8];    // [b][n][32]  k (tf32)
__device__ float g_v [BATCH * NPIX * C_IN];  // [b][n][256] v (tf32)

// ---------------------------------------------------------------------------
// helpers
// ---------------------------------------------------------------------------
__device__ __forceinline__ float to_tf32(float f) {
    uint32_t u;
    asm("cvt.rna.tf32.f32 %0, %1;" : "=r"(u) : "f"(f));
    return __uint_as_float(u);
}
__device__ __forceinline__ uint32_t smem_u32(const void* p) {
    uint32_t a;
    asm("{ .reg .u64 t; cvta.to.shared.u64 t, %1; cvt.u32.u64 %0, t; }"
        : "=r"(a) : "l"(p));
    return a;
}
__device__ __forceinline__ void mma16n8k8(float* d, const float* a, const float* b) {
    asm volatile("mma.sync.aligned.m16n8k8.row.col.f32.tf32.tf32.f32 "
        "{%0,%1,%2,%3}, {%4,%5,%6,%7}, {%8,%9}, {%0,%1,%2,%3};"
        : "+f"(d[0]), "+f"(d[1]), "+f"(d[2]), "+f"(d[3])
        : "r"(__float_as_uint(a[0])), "r"(__float_as_uint(a[1])),
          "r"(__float_as_uint(a[2])), "r"(__float_as_uint(a[3])),
          "r"(__float_as_uint(b[0])), "r"(__float_as_uint(b[1])));
}
__device__ __forceinline__ void cp16(uint32_t dst, const void* src) {
    asm volatile("cp.async.cg.shared.global [%0], [%1], 16;" :: "r"(dst), "l"(src));
}
#define CP_COMMIT() asm volatile("cp.async.commit_group;" ::: "memory")
#define CP_WAIT1()  asm volatile("cp.async.wait_group 1;" ::: "memory")
#define CP_WAIT0()  asm volatile("cp.async.wait_group 0;" ::: "memory")

// ---------------------------------------------------------------------------
// mma projections.  out^T orientation: A = x^T (m=pixel, k=channel),
// B = W (n=out-channel, k=channel).  C-fragment rows = pixels -> stores
// land in [n][D] layout coalesced.
// x tile: xs[32 c][136 pad]   (pad 136 -> banks t*8+g, conflict-free)
// W tile: ws[D  ][36 pad]     (banks g*4+t, conflict-free)
// ---------------------------------------------------------------------------
constexpr int PX_STRIDE = 136;
constexpr int PX_BUF    = 32 * PX_STRIDE;          // 4352 floats

// ---- fused q+k projection: CTA = [128 n][64 d] (d half 0 = q, 1 = k) ----
constexpr int QK_WS    = 2 * PX_BUF;               // 8704
constexpr int QK_WBUF  = 64 * 36;                  // 2304
constexpr int QK_SMEM  = (2 * PX_BUF + 2 * QK_WBUF) * 4;   // 53248 B

__global__ void __launch_bounds__(256, 2) proj_qk_mma(
    const float* __restrict__ x,
    const float* __restrict__ Wq, const float* __restrict__ bq,
    const float* __restrict__ Wk, const float* __restrict__ bk)
{
    extern __shared__ float sm[];
    const int tid = threadIdx.x, lane = tid & 31, wid = tid >> 5;
    const int b = blockIdx.z, n0 = blockIdx.x * 128;
    const int m0 = (wid >> 1) * 32;
    const int dsel = wid & 1;
    const int g = lane >> 2, t = lane & 3;
    const uint32_t sb = smem_u32(sm);
    const float* xb = x + (size_t)b * C_IN * NPIX;

    #pragma unroll
    for (int pb = 0; pb < 2; pb++) {
        const int kt = pb * 32;
        #pragma unroll
        for (int i = tid; i < 1024; i += 256) {
            int r = i >> 5, cg = i & 31;
            cp16(sb + (uint32_t)(pb * PX_BUF + r * PX_STRIDE + cg * 4) * 4,
                 xb + (size_t)(kt + r) * NPIX + n0 + cg * 4);
        }
        #pragma unroll
        for (int i = tid; i < 512; i += 256) {
            int r = i >> 3, cg = i & 7;
            const float* src = (r < 32)
                ? Wq + (size_t)r * C_IN + kt + cg * 4
                : Wk + (size_t)(r - 32) * C_IN + kt + cg * 4;
            cp16(sb + (uint32_t)(QK_WS + pb * QK_WBUF + r * 36 + cg * 4) * 4, src);
        }
        CP_COMMIT();
    }

    float acc[2][4][4] = {};

    #pragma unroll 1
    for (int j = 0; j < 8; j++) {
        if (j < 7) { CP_WAIT1(); } else { CP_WAIT0(); }
        __syncthreads();
        const int buf = j & 1;
        const float* xs = sm + buf * PX_BUF;
        const float* ws = sm + QK_WS + buf * QK_WBUF + dsel * 32 * 36;

        #pragma unroll
        for (int k8 = 0; k8 < 4; k8++) {
            const int k = k8 * 8 + t;
            float a0[4], a1[4];
            a0[0] = xs[k * PX_STRIDE + m0 + g];
            a0[1] = xs[k * PX_STRIDE + m0 + g + 8];
            a0[2] = xs[(k + 4) * PX_STRIDE + m0 + g];
            a0[3] = xs[(k + 4) * PX_STRIDE + m0 + g + 8];
            a1[0] = xs[k * PX_STRIDE + m0 + g + 16];
            a1[1] = xs[k * PX_STRIDE + m0 + g + 24];
            a1[2] = xs[(k + 4) * PX_STRIDE + m0 + g + 16];
            a1[3] = xs[(k + 4) * PX_STRIDE + m0 + g + 24];
            #pragma unroll
            for (int n8 = 0; n8 < 4; n8++) {
                float bb[2];
                bb[0] = ws[(n8 * 8 + g) * 36 + k];
                bb[1] = ws[(n8 * 8 + g) * 36 + k + 4];
                mma16n8k8(acc[0][n8], a0, bb);
                mma16n8k8(acc[1][n8], a1, bb);
            }
        }
        __syncthreads();

        if (j + 2 < 8) {
            const int kt = (j + 2) * 32;
            #pragma unroll
            for (int i = tid; i < 1024; i += 256) {
                int r = i >> 5, cg = i & 31;
                cp16(sb + (uint32_t)(buf * PX_BUF + r * PX_STRIDE + cg * 4) * 4,
                     xb + (size_t)(kt + r) * NPIX + n0 + cg * 4);
            }
            #pragma unroll
            for (int i = tid; i < 512; i += 256) {
                int r = i >> 3, cg = i & 7;
                const float* src = (r < 32)
                    ? Wq + (size_t)r * C_IN + kt + cg * 4
                    : Wk + (size_t)(r - 32) * C_IN + kt + cg * 4;
                cp16(sb + (uint32_t)(QK_WS + buf * QK_WBUF + r * 36 + cg * 4) * 4, src);
            }
            CP_COMMIT();
        }
    }

    const float* bias = dsel ? bk : bq;
    float* outp = dsel ? g_kt : g_qt;
    #pragma unroll
    for (int mt2 = 0; mt2 < 2; mt2++) {
        const int row = n0 + m0 + mt2 * 16 + g;
        #pragma unroll
        for (int n8 = 0; n8 < 4; n8++) {
            const int col = n8 * 8 + 2 * t;
            float b0 = bias[col], b1 = bias[col + 1];
            float2 lo = make_float2(to_tf32(acc[mt2][n8][0] + b0),
                                    to_tf32(acc[mt2][n8][1] + b1));
            float2 hi = make_float2(to_tf32(acc[mt2][n8][2] + b0),
                                    to_tf32(acc[mt2][n8][3] + b1));
            *(float2*)&outp[((size_t)b * NPIX + row) * D8 + col] = lo;
            *(float2*)&outp[((size_t)b * NPIX + row + 8) * D8 + col] = hi;
        }
    }
}

// ---- v projection: CTA = [128 n][128 d], grid.y = 2 ----
constexpr int PV_WS   = 2 * PX_BUF;                // 8704
constexpr int PV_WBUF = 128 * 36;                  // 4608
constexpr int PV_SMEM = (2 * PX_BUF + 2 * PV_WBUF) * 4;   // 71680 B

__global__ void __launch_bounds__(256, 2) proj_v_mma(
    const float* __restrict__ x,
    const float* __restrict__ Wv, const float* __restrict__ bv)
{
    extern __shared__ float sm[];
    const int tid = threadIdx.x, lane = tid & 31, wid = tid >> 5;
    const int b = blockIdx.z, n0 = blockIdx.x * 128, d0 = blockIdx.y * 128;
    const int m0 = (wid >> 1) * 32;
    const int dcol = (wid & 1) * 64;
    const int g = lane >> 2, t = lane & 3;
    const uint32_t sb = smem_u32(sm);
    const float* xb = x + (size_t)b * C_IN * NPIX;

    #pragma unroll
    for (int pb = 0; pb < 2; pb++) {
        const int kt = pb * 32;
        #pragma unroll
        for (int i = tid; i < 1024; i += 256) {
            int r = i >> 5, cg = i & 31;
            cp16(sb + (uint32_t)(pb * PX_BUF + r * PX_STRIDE + cg * 4) * 4,
                 xb + (size_t)(kt + r) * NPIX + n0 + cg * 4);
        }
        #pragma unroll
        for (int i = tid; i < 1024; i += 256) {
            int r = i >> 3, cg = i & 7;
            cp16(sb + (uint32_t)(PV_WS + pb * PV_WBUF + r * 36 + cg * 4) * 4,
                 Wv + (size_t)(d0 + r) * C_IN + kt + cg * 4);
        }
        CP_COMMIT();
    }

    float acc[2][8][4] = {};

    #pragma unroll 1
    for (int j = 0; j < 8; j++) {
        if (j < 7) { CP_WAIT1(); } else { CP_WAIT0(); }
        __syncthreads();
        const int buf = j & 1;
        const float* xs = sm + buf * PX_BUF;
        const float* ws = sm + PV_WS + buf * PV_WBUF + dcol * 36;

        #pragma unroll
        for (int k8 = 0; k8 < 4; k8++) {
            const int k = k8 * 8 + t;
            float a0[4], a1[4];
            a0[0] = xs[k * PX_STRIDE + m0 + g];
            a0[1] = xs[k * PX_STRIDE + m0 + g + 8];
            a0[2] = xs[(k + 4) * PX_STRIDE + m0 + g];
            a0[3] = xs[(k + 4) * PX_STRIDE + m0 + g + 8];
            a1[0] = xs[k * PX_STRIDE + m0 + g + 16];
            a1[1] = xs[k * PX_STRIDE + m0 + g + 24];
            a1[2] = xs[(k + 4) * PX_STRIDE + m0 + g + 16];
            a1[3] = xs[(k + 4) * PX_STRIDE + m0 + g + 24];
            #pragma unroll
            for (int n8 = 0; n8 < 8; n8++) {
                float bb[2];
                bb[0] = ws[(n8 * 8 + g) * 36 + k];
                bb[1] = ws[(n8 * 8 + g) * 36 + k + 4];
                mma16n8k8(acc[0][n8], a0, bb);
                mma16n8k8(acc[1][n8], a1, bb);
            }
        }
        __syncthreads();

        if (j + 2 < 8) {
            const int kt = (j + 2) * 32;
            #pragma unroll
            for (int i = tid; i < 1024; i += 256) {
                int r = i >> 5, cg = i & 31;
                cp16(sb + (uint32_t)(buf * PX_BUF + r * PX_STRIDE + cg * 4) * 4,
                     xb + (size_t)(kt + r) * NPIX + n0 + cg * 4);
            }
            #pragma unroll
            for (int i = tid; i < 1024; i += 256) {
                int r = i >> 3, cg = i & 7;
                cp16(sb + (uint32_t)(PV_WS + buf * PV_WBUF + r * 36 + cg * 4) * 4,
                     Wv + (size_t)(d0 + r) * C_IN + kt + cg * 4);
            }
            CP_COMMIT();
        }
    }

    #pragma unroll
    for (int mt2 = 0; mt2 < 2; mt2++) {
        const int row = n0 + m0 + mt2 * 16 + g;
        #pragma unroll
        for (int n8 = 0; n8 < 8; n8++) {
            const int col = d0 + dcol + n8 * 8 + 2 * t;
            float b0 = bv[col], b1 = bv[col + 1];
            float2 lo = make_float2(to_tf32(acc[mt2][n8][0] + b0),
                                    to_tf32(acc[mt2][n8][1] + b1));
            float2 hi = make_float2(to_tf32(acc[mt2][n8][2] + b0),
                                    to_tf32(acc[mt2][n8][3] + b1));
            *(float2*)&g_v[((size_t)b * NPIX + row) * C_IN + col] = lo;
            *(float2*)&g_v[((size_t)b * NPIX + row + 8) * C_IN + col] = hi;
        }
    }
}

// ---------------------------------------------------------------------------
// mma.sync tf32 flash attention.
// CTA = (batch, 128 query rows), 256 threads = 8 warps.
// warp -> row-group (wid>>1)*32, channel half (wid&1)*128.
// V tile now [64 keys][256 ch] (pad 264 -> B-reads bank t*8+g conflict-free).
// SMEM (floats): Qs[128][36] | Ks[2][64][36] | Vs[2][64][264] = 172032 B
// ---------------------------------------------------------------------------
constexpr int QS_F = 0;
constexpr int KS_F = 128 * 36;                  // 4608
constexpr int VS_F = KS_F + 2 * 64 * 36;        // 9216
constexpr int VBUF = 64 * 264;                  // 16896
constexpr int SMEM_ATTN = (VS_F + 2 * VBUF) * 4;   // 172032

__global__ void __launch_bounds__(256, 1) attn_mma_kernel(
    const float* __restrict__ x, const float* __restrict__ gamma_p,
    float* __restrict__ out)
{
    extern __shared__ __align__(16) float sm[];
    const int tid  = threadIdx.x;
    const int lane = tid & 31, wid = tid >> 5;
    const int b   = blockIdx.y;
    const int nt  = blockIdx.x * MROWS;
    const int m0  = (wid >> 1) * 32;
    const int ch0 = (wid & 1) * 128;
    const int g = lane >> 2, t = lane & 3;

    const float* qt = g_qt + (size_t)b * NPIX * D8;
    const float* kq = g_kt + (size_t)b * NPIX * D8;
    const float* vb = g_v  + (size_t)b * NPIX * C_IN;

    const uint32_t sb = smem_u32(sm);

    // Q tile -> smem [128][36]
    #pragma unroll
    for (int i = tid; i < 1024; i += 256) {
        int r = i >> 3, cg = i & 7;
        *(float4*)&sm[QS_F + r * 36 + cg * 4] =
            *(const float4*)&qt[(size_t)(nt + r) * D8 + cg * 4];
    }

    // Prefetch key-tiles 0 and 1
    #pragma unroll
    for (int pb = 0; pb < 2; pb++) {
        const int mt = pb * KT;
        #pragma unroll
        for (int i = tid; i < 512; i += 256) {
            int r = i >> 3, cg = i & 7;
            cp16(sb + (uint32_t)(KS_F + pb * 2304 + r * 36 + cg * 4) * 4,
                 kq + (size_t)(mt + r) * D8 + cg * 4);
        }
        #pragma unroll
        for (int i = tid; i < 4096; i += 256) {
            int r = i >> 6, cg = i & 63;
            cp16(sb + (uint32_t)(VS_F + pb * VBUF + r * 264 + cg * 4) * 4,
                 vb + (size_t)(mt + r) * C_IN + cg * 4);
        }
        CP_COMMIT();
    }

    float o[2][16][4];
    #pragma unroll
    for (int i = 0; i < 2; i++)
        #pragma unroll
        for (int j = 0; j < 16; j++)
            #pragma unroll
            for (int k = 0; k < 4; k++) o[i][j][k] = 0.f;

    float lsum[2][2] = {{0.f, 0.f}, {0.f, 0.f}};
    const int srcA = g * 4 + (t >> 1);
    const int srcB = srcA + 2;
    const bool odd = (t & 1) != 0;

    #pragma unroll 1
    for (int tt = 0; tt < NTILES; tt++) {
        const int buf = tt & 1;
        if (tt < NTILES - 1) { CP_WAIT1(); } else { CP_WAIT0(); }
        __syncthreads();

        const float* Ks = sm + KS_F + buf * 2304;
        const float* Vs = sm + VS_F + buf * VBUF;

        // ---- QK: S[32 rows][64 keys] per warp ----
        float s[2][8][4];
        #pragma unroll
        for (int i = 0; i < 2; i++)
            #pragma unroll
            for (int j = 0; j < 8; j++)
                #pragma unroll
                for (int k = 0; k < 4; k++) s[i][j][k] = 0.f;

        #pragma unroll
        for (int sk = 0; sk < 4; sk++) {
            const int dd = sk * 8 + t;
            float a0[4], a1[4];
            a0[0] = sm[QS_F + (m0 + g) * 36 + dd];
            a0[1] = sm[QS_F + (m0 + g + 8) * 36 + dd];
            a0[2] = sm[QS_F + (m0 + g) * 36 + dd + 4];
            a0[3] = sm[QS_F + (m0 + g + 8) * 36 + dd + 4];
            a1[0] = sm[QS_F + (m0 + 16 + g) * 36 + dd];
            a1[1] = sm[QS_F + (m0 + 24 + g) * 36 + dd];
            a1[2] = sm[QS_F + (m0 + 16 + g) * 36 + dd + 4];
            a1[3] = sm[QS_F + (m0 + 24 + g) * 36 + dd + 4];
            #pragma unroll
            for (int n8 = 0; n8 < 8; n8++) {
                float bb[2];
                bb[0] = Ks[(n8 * 8 + g) * 36 + dd];
                bb[1] = Ks[(n8 * 8 + g) * 36 + dd + 4];
                mma16n8k8(s[0][n8], a0, bb);
                mma16n8k8(s[1][n8], a1, bb);
            }
        }

        // ---- softmax numerator + C-frag -> A-frag conversion (in regs) ----
        #pragma unroll
        for (int mt = 0; mt < 2; mt++) {
            #pragma unroll
            for (int k8 = 0; k8 < 8; k8++) {
                float p0 = to_tf32(__expf(s[mt][k8][0]));
                float p1 = to_tf32(__expf(s[mt][k8][1]));
                float p2 = to_tf32(__expf(s[mt][k8][2]));
                float p3 = to_tf32(__expf(s[mt][k8][3]));
                lsum[mt][0] += p0 + p1;
                lsum[mt][1] += p2 + p3;
                float u0 = __shfl_sync(0xffffffffu, p0, srcA);
                float u1 = __shfl_sync(0xffffffffu, p1, srcA);
                float u2 = __shfl_sync(0xffffffffu, p2, srcA);
                float u3 = __shfl_sync(0xffffffffu, p3, srcA);
                float w0 = __shfl_sync(0xffffffffu, p0, srcB);
                float w1 = __shfl_sync(0xffffffffu, p1, srcB);
                float w2 = __shfl_sync(0xffffffffu, p2, srcB);
                float w3 = __shfl_sync(0xffffffffu, p3, srcB);
                s[mt][k8][0] = odd ? u1 : u0;   // A[g][t]
                s[mt][k8][1] = odd ? u3 : u2;   // A[g+8][t]
                s[mt][k8][2] = odd ? w1 : w0;   // A[g][t+4]
                s[mt][k8][3] = odd ? w3 : w2;   // A[g+8][t+4]
            }
        }

        // ---- AV: O[32 rows][128 ch] += P V^T ----
        #pragma unroll
        for (int k8 = 0; k8 < 8; k8++) {
            #pragma unroll
            for (int n8 = 0; n8 < 16; n8++) {
                float bb[2];
                const int c = ch0 + n8 * 8 + g;
                bb[0] = Vs[(k8 * 8 + t) * 264 + c];
                bb[1] = Vs[(k8 * 8 + t + 4) * 264 + c];
                mma16n8k8(o[0][n8], s[0][k8], bb);
                mma16n8k8(o[1][n8], s[1][k8], bb);
            }
        }

        __syncthreads();   // all warps done reading buf before refilling it

        if (tt + 2 < NTILES) {
            const int mt = (tt + 2) * KT;
            #pragma unroll
            for (int i = tid; i < 512; i += 256) {
                int r = i >> 3, cg = i & 7;
                cp16(sb + (uint32_t)(KS_F + buf * 2304 + r * 36 + cg * 4) * 4,
                     kq + (size_t)(mt + r) * D8 + cg * 4);
            }
            #pragma unroll
            for (int i = tid; i < 4096; i += 256) {
                int r = i >> 6, cg = i & 63;
                cp16(sb + (uint32_t)(VS_F + buf * VBUF + r * 264 + cg * 4) * 4,
                     vb + (size_t)(mt + r) * C_IN + cg * 4);
            }
            CP_COMMIT();
        }
    }

    // ---- epilogue: out = gamma * O / l + x ----
    #pragma unroll
    for (int mt = 0; mt < 2; mt++)
        #pragma unroll
        for (int h = 0; h < 2; h++) {
            lsum[mt][h] += __shfl_xor_sync(0xffffffffu, lsum[mt][h], 1);
            lsum[mt][h] += __shfl_xor_sync(0xffffffffu, lsum[mt][h], 2);
        }
    const float gma = gamma_p[0];
    float inv[2][2];
    #pragma unroll
    for (int mt = 0; mt < 2; mt++)
        #pragma unroll
        for (int h = 0; h < 2; h++) inv[mt][h] = gma / lsum[mt][h];

    #pragma unroll
    for (int mt = 0; mt < 2; mt++) {
        const int rbase = nt + m0 + mt * 16 + g;
        #pragma unroll
        for (int n8 = 0; n8 < 16; n8++) {
            const int c0 = ch0 + n8 * 8 + 2 * t;
            size_t gi = ((size_t)b * C_IN + c0) * NPIX + rbase;
            out[gi]            = o[mt][n8][0] * inv[mt][0] + x[gi];
            out[gi + NPIX]     = o[mt][n8][1] * inv[mt][0] + x[gi + NPIX];
            out[gi + 8]        = o[mt][n8][2] * inv[mt][1] + x[gi + 8];
            out[gi + NPIX + 8] = o[mt][n8][3] * inv[mt][1] + x[gi + NPIX + 8];
        }
    }
}

// ---------------------------------------------------------------------------
extern "C" void kernel_launch(void* const* d_in, const int* in_sizes, int n_in,
                              void* d_out, int out_size)
{
    const float* x     = (const float*)d_in[0];
    const float* Wq    = (const float*)d_in[1];
    const float* bq    = (const float*)d_in[2];
    const float* Wk    = (const float*)d_in[3];
    const float* bk    = (const float*)d_in[4];
    const float* Wv    = (const float*)d_in[5];
    const float* bv    = (const float*)d_in[6];
    const float* gamma = (const float*)d_in[7];
    float* out = (float*)d_out;

    static bool attr_set = false;
    if (!attr_set) {
        cudaFuncSetAttribute(proj_qk_mma,
                             cudaFuncAttributeMaxDynamicSharedMemorySize, QK_SMEM);
        cudaFuncSetAttribute(proj_v_mma,
                             cudaFuncAttributeMaxDynamicSharedMemorySize, PV_SMEM);
        cudaFuncSetAttribute(attn_mma_kernel,
                             cudaFuncAttributeMaxDynamicSharedMemorySize, SMEM_ATTN);
        attr_set = true;
    }

    proj_qk_mma<<<dim3(NPIX / 128, 1, BATCH), 256, QK_SMEM>>>(x, Wq, bq, Wk, bk);
    proj_v_mma <<<dim3(NPIX / 128, 2, BATCH), 256, PV_SMEM>>>(x, Wv, bv);
    attn_mma_kernel<<<dim3(NPIX / MROWS, BATCH), 256, SMEM_ATTN>>>(x, gamma, out);
}

// round 8
// speedup vs baseline: 11.2982x; 1.4211x over previous
#include <cuda_runtime.h>
#include <cuda_bf16.h>
#include <cstdint>
#include <cstddef>

#define BATCH 32
#define C_IN  256
#define NPIX  1024
#define D8    32
#define KT    64
#define NTILES 16
#define MROWS 128

// Scratch (device globals: allocation-free)
__device__ float g_qt[BATCH * NPIX * D8];            // [b][n][32]  q (tf32)
__device__ float g_kt[BATCH * NPIX * D8];            // [b][n][32]  k (tf32)
__device__ __nv_bfloat16 g_v[BATCH * C_IN * NPIX];   // [b][c][n]   v (bf16)

// ---------------------------------------------------------------------------
// helpers
// ---------------------------------------------------------------------------
__device__ __forceinline__ float to_tf32(float f) {
    uint32_t u;
    asm("cvt.rna.tf32.f32 %0, %1;" : "=r"(u) : "f"(f));
    return __uint_as_float(u);
}
__device__ __forceinline__ uint32_t bf2(float lo, float hi) {
    uint32_t r;
    asm("cvt.rn.bf16x2.f32 %0, %1, %2;" : "=r"(r) : "f"(hi), "f"(lo));
    return r;
}
__device__ __forceinline__ uint32_t smem_u32(const void* p) {
    uint32_t a;
    asm("{ .reg .u64 t; cvta.to.shared.u64 t, %1; cvt.u32.u64 %0, t; }"
        : "=r"(a) : "l"(p));
    return a;
}
__device__ __forceinline__ void mma16n8k8(float* d, const float* a, const float* b) {
    asm volatile("mma.sync.aligned.m16n8k8.row.col.f32.tf32.tf32.f32 "
        "{%0,%1,%2,%3}, {%4,%5,%6,%7}, {%8,%9}, {%0,%1,%2,%3};"
        : "+f"(d[0]), "+f"(d[1]), "+f"(d[2]), "+f"(d[3])
        : "r"(__float_as_uint(a[0])), "r"(__float_as_uint(a[1])),
          "r"(__float_as_uint(a[2])), "r"(__float_as_uint(a[3])),
          "r"(__float_as_uint(b[0])), "r"(__float_as_uint(b[1])));
}
__device__ __forceinline__ void mma_bf16(float* d, const uint32_t* a,
                                         uint32_t b0, uint32_t b1) {
    asm volatile("mma.sync.aligned.m16n8k16.row.col.f32.bf16.bf16.f32 "
        "{%0,%1,%2,%3}, {%4,%5,%6,%7}, {%8,%9}, {%0,%1,%2,%3};"
        : "+f"(d[0]), "+f"(d[1]), "+f"(d[2]), "+f"(d[3])
        : "r"(a[0]), "r"(a[1]), "r"(a[2]), "r"(a[3]), "r"(b0), "r"(b1));
}
__device__ __forceinline__ void cp16(uint32_t dst, const void* src) {
    asm volatile("cp.async.cg.shared.global [%0], [%1], 16;" :: "r"(dst), "l"(src));
}
#define CP_COMMIT() asm volatile("cp.async.commit_group;" ::: "memory")
#define CP_WAIT1()  asm volatile("cp.async.wait_group 1;" ::: "memory")
#define CP_WAIT0()  asm volatile("cp.async.wait_group 0;" ::: "memory")

// ---------------------------------------------------------------------------
// mma projections (tf32): A = x^T (m=pixel, k=channel), B = W.
// x tile: xs[32 c][136 pad], W tile: ws[D][36 pad] — both conflict-free.
// ---------------------------------------------------------------------------
constexpr int PX_STRIDE = 136;
constexpr int PX_BUF    = 32 * PX_STRIDE;          // 4352 floats

// ---- fused q+k projection: CTA = [128 n][64 d] (d half 0 = q, 1 = k) ----
constexpr int QK_WS    = 2 * PX_BUF;               // 8704
constexpr int QK_WBUF  = 64 * 36;                  // 2304
constexpr int QK_SMEM  = (2 * PX_BUF + 2 * QK_WBUF) * 4;   // 53248 B

__global__ void __launch_bounds__(256, 2) proj_qk_mma(
    const float* __restrict__ x,
    const float* __restrict__ Wq, const float* __restrict__ bq,
    const float* __restrict__ Wk, const float* __restrict__ bk)
{
    extern __shared__ float sm[];
    const int tid = threadIdx.x, lane = tid & 31, wid = tid >> 5;
    const int b = blockIdx.z, n0 = blockIdx.x * 128;
    const int m0 = (wid >> 1) * 32;
    const int dsel = wid & 1;
    const int g = lane >> 2, t = lane & 3;
    const uint32_t sb = smem_u32(sm);
    const float* xb = x + (size_t)b * C_IN * NPIX;

    #pragma unroll
    for (int pb = 0; pb < 2; pb++) {
        const int kt = pb * 32;
        #pragma unroll
        for (int i = tid; i < 1024; i += 256) {
            int r = i >> 5, cg = i & 31;
            cp16(sb + (uint32_t)(pb * PX_BUF + r * PX_STRIDE + cg * 4) * 4,
                 xb + (size_t)(kt + r) * NPIX + n0 + cg * 4);
        }
        #pragma unroll
        for (int i = tid; i < 512; i += 256) {
            int r = i >> 3, cg = i & 7;
            const float* src = (r < 32)
                ? Wq + (size_t)r * C_IN + kt + cg * 4
                : Wk + (size_t)(r - 32) * C_IN + kt + cg * 4;
            cp16(sb + (uint32_t)(QK_WS + pb * QK_WBUF + r * 36 + cg * 4) * 4, src);
        }
        CP_COMMIT();
    }

    float acc[2][4][4] = {};

    #pragma unroll 1
    for (int j = 0; j < 8; j++) {
        if (j < 7) { CP_WAIT1(); } else { CP_WAIT0(); }
        __syncthreads();
        const int buf = j & 1;
        const float* xs = sm + buf * PX_BUF;
        const float* ws = sm + QK_WS + buf * QK_WBUF + dsel * 32 * 36;

        #pragma unroll
        for (int k8 = 0; k8 < 4; k8++) {
            const int k = k8 * 8 + t;
            float a0[4], a1[4];
            a0[0] = xs[k * PX_STRIDE + m0 + g];
            a0[1] = xs[k * PX_STRIDE + m0 + g + 8];
            a0[2] = xs[(k + 4) * PX_STRIDE + m0 + g];
            a0[3] = xs[(k + 4) * PX_STRIDE + m0 + g + 8];
            a1[0] = xs[k * PX_STRIDE + m0 + g + 16];
            a1[1] = xs[k * PX_STRIDE + m0 + g + 24];
            a1[2] = xs[(k + 4) * PX_STRIDE + m0 + g + 16];
            a1[3] = xs[(k + 4) * PX_STRIDE + m0 + g + 24];
            #pragma unroll
            for (int n8 = 0; n8 < 4; n8++) {
                float bb[2];
                bb[0] = ws[(n8 * 8 + g) * 36 + k];
                bb[1] = ws[(n8 * 8 + g) * 36 + k + 4];
                mma16n8k8(acc[0][n8], a0, bb);
                mma16n8k8(acc[1][n8], a1, bb);
            }
        }
        __syncthreads();

        if (j + 2 < 8) {
            const int kt = (j + 2) * 32;
            #pragma unroll
            for (int i = tid; i < 1024; i += 256) {
                int r = i >> 5, cg = i & 31;
                cp16(sb + (uint32_t)(buf * PX_BUF + r * PX_STRIDE + cg * 4) * 4,
                     xb + (size_t)(kt + r) * NPIX + n0 + cg * 4);
            }
            #pragma unroll
            for (int i = tid; i < 512; i += 256) {
                int r = i >> 3, cg = i & 7;
                const float* src = (r < 32)
                    ? Wq + (size_t)r * C_IN + kt + cg * 4
                    : Wk + (size_t)(r - 32) * C_IN + kt + cg * 4;
                cp16(sb + (uint32_t)(QK_WS + buf * QK_WBUF + r * 36 + cg * 4) * 4, src);
            }
            CP_COMMIT();
        }
    }

    const float* bias = dsel ? bk : bq;
    float* outp = dsel ? g_kt : g_qt;
    #pragma unroll
    for (int mt2 = 0; mt2 < 2; mt2++) {
        const int row = n0 + m0 + mt2 * 16 + g;
        #pragma unroll
        for (int n8 = 0; n8 < 4; n8++) {
            const int col = n8 * 8 + 2 * t;
            float b0 = bias[col], b1 = bias[col + 1];
            float2 lo = make_float2(to_tf32(acc[mt2][n8][0] + b0),
                                    to_tf32(acc[mt2][n8][1] + b1));
            float2 hi = make_float2(to_tf32(acc[mt2][n8][2] + b0),
                                    to_tf32(acc[mt2][n8][3] + b1));
            *(float2*)&outp[((size_t)b * NPIX + row) * D8 + col] = lo;
            *(float2*)&outp[((size_t)b * NPIX + row + 8) * D8 + col] = hi;
        }
    }
}

// ---- v projection: CTA = [128 n][128 d], grid.y = 2; bf16 [c][n] output ----
constexpr int PV_WS   = 2 * PX_BUF;                // 8704
constexpr int PV_WBUF = 128 * 36;                  // 4608
constexpr int PV_SMEM = (2 * PX_BUF + 2 * PV_WBUF) * 4;   // 71680 B

__global__ void __launch_bounds__(256, 2) proj_v_mma(
    const float* __restrict__ x,
    const float* __restrict__ Wv, const float* __restrict__ bv)
{
    extern __shared__ float sm[];
    const int tid = threadIdx.x, lane = tid & 31, wid = tid >> 5;
    const int b = blockIdx.z, n0 = blockIdx.x * 128, d0 = blockIdx.y * 128;
    const int m0 = (wid >> 1) * 32;
    const int dcol = (wid & 1) * 64;
    const int g = lane >> 2, t = lane & 3;
    const uint32_t sb = smem_u32(sm);
    const float* xb = x + (size_t)b * C_IN * NPIX;

    #pragma unroll
    for (int pb = 0; pb < 2; pb++) {
        const int kt = pb * 32;
        #pragma unroll
        for (int i = tid; i < 1024; i += 256) {
            int r = i >> 5, cg = i & 31;
            cp16(sb + (uint32_t)(pb * PX_BUF + r * PX_STRIDE + cg * 4) * 4,
                 xb + (size_t)(kt + r) * NPIX + n0 + cg * 4);
        }
        #pragma unroll
        for (int i = tid; i < 1024; i += 256) {
            int r = i >> 3, cg = i & 7;
            cp16(sb + (uint32_t)(PV_WS + pb * PV_WBUF + r * 36 + cg * 4) * 4,
                 Wv + (size_t)(d0 + r) * C_IN + kt + cg * 4);
        }
        CP_COMMIT();
    }

    float acc[2][8][4] = {};

    #pragma unroll 1
    for (int j = 0; j < 8; j++) {
        if (j < 7) { CP_WAIT1(); } else { CP_WAIT0(); }
        __syncthreads();
        const int buf = j & 1;
        const float* xs = sm + buf * PX_BUF;
        const float* ws = sm + PV_WS + buf * PV_WBUF + dcol * 36;

        #pragma unroll
        for (int k8 = 0; k8 < 4; k8++) {
            const int k = k8 * 8 + t;
            float a0[4], a1[4];
            a0[0] = xs[k * PX_STRIDE + m0 + g];
            a0[1] = xs[k * PX_STRIDE + m0 + g + 8];
            a0[2] = xs[(k + 4) * PX_STRIDE + m0 + g];
            a0[3] = xs[(k + 4) * PX_STRIDE + m0 + g + 8];
            a1[0] = xs[k * PX_STRIDE + m0 + g + 16];
            a1[1] = xs[k * PX_STRIDE + m0 + g + 24];
            a1[2] = xs[(k + 4) * PX_STRIDE + m0 + g + 16];
            a1[3] = xs[(k + 4) * PX_STRIDE + m0 + g + 24];
            #pragma unroll
            for (int n8 = 0; n8 < 8; n8++) {
                float bb[2];
                bb[0] = ws[(n8 * 8 + g) * 36 + k];
                bb[1] = ws[(n8 * 8 + g) * 36 + k + 4];
                mma16n8k8(acc[0][n8], a0, bb);
                mma16n8k8(acc[1][n8], a1, bb);
            }
        }
        __syncthreads();

        if (j + 2 < 8) {
            const int kt = (j + 2) * 32;
            #pragma unroll
            for (int i = tid; i < 1024; i += 256) {
                int r = i >> 5, cg = i & 31;
                cp16(sb + (uint32_t)(buf * PX_BUF + r * PX_STRIDE + cg * 4) * 4,
                     xb + (size_t)(kt + r) * NPIX + n0 + cg * 4);
            }
            #pragma unroll
            for (int i = tid; i < 1024; i += 256) {
                int r = i >> 3, cg = i & 7;
                cp16(sb + (uint32_t)(PV_WS + buf * PV_WBUF + r * 36 + cg * 4) * 4,
                     Wv + (size_t)(d0 + r) * C_IN + kt + cg * 4);
            }
            CP_COMMIT();
        }
    }

    // Epilogue: bf16 transpose via SMEM -> coalesced [c][n] global stores
    __syncthreads();
    __nv_bfloat16* Ts = (__nv_bfloat16*)sm;   // [128 c][136 n]
    #pragma unroll
    for (int mt2 = 0; mt2 < 2; mt2++) {
        const int row = m0 + mt2 * 16 + g;    // local pixel 0..127
        #pragma unroll
        for (int n8 = 0; n8 < 8; n8++) {
            const int colL = dcol + n8 * 8 + 2 * t;   // local channel
            float b0 = bv[d0 + colL], b1 = bv[d0 + colL + 1];
            Ts[colL * 136 + row]           = __float2bfloat16(acc[mt2][n8][0] + b0);
            Ts[(colL + 1) * 136 + row]     = __float2bfloat16(acc[mt2][n8][1] + b1);
            Ts[colL * 136 + row + 8]       = __float2bfloat16(acc[mt2][n8][2] + b0);
            Ts[(colL + 1) * 136 + row + 8] = __float2bfloat16(acc[mt2][n8][3] + b1);
        }
    }
    __syncthreads();
    #pragma unroll
    for (int i = tid; i < 128 * 64; i += 256) {
        int c = i >> 6, w = i & 63;
        ((uint32_t*)&g_v[((size_t)b * C_IN + d0 + c) * NPIX + n0])[w] =
            ((const uint32_t*)&Ts[c * 136])[w];
    }
}

// ---------------------------------------------------------------------------
// Flash attention: QK in tf32 mma, AV in bf16 mma (m16n8k16).
// QK C-fragment layout == bf16 A-fragment layout -> zero-shuffle P handoff.
// SMEM: Qs[128][36] f32 | Ks[2][64][36] f32 | Vs[2][256 ch][72 keys] bf16
// ---------------------------------------------------------------------------
constexpr int QS_F = 0;
constexpr int KS_F = 128 * 36;                       // 4608 floats
constexpr int VS_B = (KS_F + 2 * 64 * 36) * 4;       // 36864 bytes
constexpr int VBUF_B = 256 * 72 * 2;                 // 36864 bytes
constexpr int SMEM_ATTN = VS_B + 2 * VBUF_B;         // 110592 B

__global__ void __launch_bounds__(256, 1) attn_mma_kernel(
    const float* __restrict__ x, const float* __restrict__ gamma_p,
    float* __restrict__ out)
{
    extern __shared__ __align__(16) char smc[];
    float* sm = (float*)smc;
    const int tid  = threadIdx.x;
    const int lane = tid & 31, wid = tid >> 5;
    const int b   = blockIdx.y;
    const int nt  = blockIdx.x * MROWS;
    const int m0  = (wid >> 1) * 32;
    const int ch0 = (wid & 1) * 128;
    const int g = lane >> 2, t = lane & 3;

    const float* qt = g_qt + (size_t)b * NPIX * D8;
    const float* kq = g_kt + (size_t)b * NPIX * D8;
    const __nv_bfloat16* vb = g_v + (size_t)b * C_IN * NPIX;

    const uint32_t sb = smem_u32(smc);

    // Q tile -> smem [128][36] f32
    #pragma unroll
    for (int i = tid; i < 1024; i += 256) {
        int r = i >> 3, cg = i & 7;
        *(float4*)&sm[QS_F + r * 36 + cg * 4] =
            *(const float4*)&qt[(size_t)(nt + r) * D8 + cg * 4];
    }

    // Prefetch key-tiles 0 and 1
    #pragma unroll
    for (int pb = 0; pb < 2; pb++) {
        const int mt = pb * KT;
        #pragma unroll
        for (int i = tid; i < 512; i += 256) {
            int r = i >> 3, cg = i & 7;
            cp16(sb + (uint32_t)(KS_F + pb * 2304 + r * 36 + cg * 4) * 4,
                 kq + (size_t)(mt + r) * D8 + cg * 4);
        }
        #pragma unroll
        for (int i = tid; i < 2048; i += 256) {
            int c = i >> 3, m4 = i & 7;
            cp16(sb + (uint32_t)(VS_B + pb * VBUF_B + c * 144 + m4 * 16),
                 vb + (size_t)c * NPIX + mt + m4 * 8);
        }
        CP_COMMIT();
    }

    float o[2][16][4];
    #pragma unroll
    for (int i = 0; i < 2; i++)
        #pragma unroll
        for (int j = 0; j < 16; j++)
            #pragma unroll
            for (int k = 0; k < 4; k++) o[i][j][k] = 0.f;

    float lsum[2][2] = {{0.f, 0.f}, {0.f, 0.f}};

    #pragma unroll 1
    for (int tt = 0; tt < NTILES; tt++) {
        const int buf = tt & 1;
        if (tt < NTILES - 1) { CP_WAIT1(); } else { CP_WAIT0(); }
        __syncthreads();

        const float* Ks = sm + KS_F + buf * 2304;
        const uint32_t* V32 = (const uint32_t*)(smc + VS_B + buf * VBUF_B);

        // ---- QK (tf32): S[32 rows][64 keys] per warp ----
        float s[2][8][4];
        #pragma unroll
        for (int i = 0; i < 2; i++)
            #pragma unroll
            for (int j = 0; j < 8; j++)
                #pragma unroll
                for (int k = 0; k < 4; k++) s[i][j][k] = 0.f;

        #pragma unroll
        for (int sk = 0; sk < 4; sk++) {
            const int dd = sk * 8 + t;
            float a0[4], a1[4];
            a0[0] = sm[QS_F + (m0 + g) * 36 + dd];
            a0[1] = sm[QS_F + (m0 + g + 8) * 36 + dd];
            a0[2] = sm[QS_F + (m0 + g) * 36 + dd + 4];
            a0[3] = sm[QS_F + (m0 + g + 8) * 36 + dd + 4];
            a1[0] = sm[QS_F + (m0 + 16 + g) * 36 + dd];
            a1[1] = sm[QS_F + (m0 + 24 + g) * 36 + dd];
            a1[2] = sm[QS_F + (m0 + 16 + g) * 36 + dd + 4];
            a1[3] = sm[QS_F + (m0 + 24 + g) * 36 + dd + 4];
            #pragma unroll
            for (int n8 = 0; n8 < 8; n8++) {
                float bb[2];
                bb[0] = Ks[(n8 * 8 + g) * 36 + dd];
                bb[1] = Ks[(n8 * 8 + g) * 36 + dd + 4];
                mma16n8k8(s[0][n8], a0, bb);
                mma16n8k8(s[1][n8], a1, bb);
            }
        }

        // ---- exp + pack: C-frags -> bf16 A-frags (no shuffles) ----
        uint32_t pa[2][4][4];
        #pragma unroll
        for (int mt2 = 0; mt2 < 2; mt2++) {
            #pragma unroll
            for (int n8 = 0; n8 < 8; n8++) {
                float p0 = __expf(s[mt2][n8][0]);
                float p1 = __expf(s[mt2][n8][1]);
                float p2 = __expf(s[mt2][n8][2]);
                float p3 = __expf(s[mt2][n8][3]);
                lsum[mt2][0] += p0 + p1;
                lsum[mt2][1] += p2 + p3;
                pa[mt2][n8 >> 1][(n8 & 1) * 2 + 0] = bf2(p0, p1);
                pa[mt2][n8 >> 1][(n8 & 1) * 2 + 1] = bf2(p2, p3);
            }
        }

        // ---- AV (bf16): O[32 rows][128 ch] += P V^T ----
        #pragma unroll
        for (int k8 = 0; k8 < 4; k8++) {
            #pragma unroll
            for (int n8 = 0; n8 < 16; n8++) {
                const int c = ch0 + n8 * 8 + g;
                uint32_t b0 = V32[c * 36 + k8 * 8 + t];
                uint32_t b1 = V32[c * 36 + k8 * 8 + t + 4];
                mma_bf16(o[0][n8], pa[0][k8], b0, b1);
                mma_bf16(o[1][n8], pa[1][k8], b0, b1);
            }
        }

        __syncthreads();   // all warps done reading buf before refilling it

        if (tt + 2 < NTILES) {
            const int mt = (tt + 2) * KT;
            #pragma unroll
            for (int i = tid; i < 512; i += 256) {
                int r = i >> 3, cg = i & 7;
                cp16(sb + (uint32_t)(KS_F + buf * 2304 + r * 36 + cg * 4) * 4,
                     kq + (size_t)(mt + r) * D8 + cg * 4);
            }
            #pragma unroll
            for (int i = tid; i < 2048; i += 256) {
                int c = i >> 3, m4 = i & 7;
                cp16(sb + (uint32_t)(VS_B + buf * VBUF_B + c * 144 + m4 * 16),
                     vb + (size_t)c * NPIX + mt + m4 * 8);
            }
            CP_COMMIT();
        }
    }

    // ---- epilogue: out = gamma * O / l + x ----
    #pragma unroll
    for (int mt2 = 0; mt2 < 2; mt2++)
        #pragma unroll
        for (int h = 0; h < 2; h++) {
            lsum[mt2][h] += __shfl_xor_sync(0xffffffffu, lsum[mt2][h], 1);
            lsum[mt2][h] += __shfl_xor_sync(0xffffffffu, lsum[mt2][h], 2);
        }
    const float gma = gamma_p[0];
    float inv[2][2];
    #pragma unroll
    for (int mt2 = 0; mt2 < 2; mt2++)
        #pragma unroll
        for (int h = 0; h < 2; h++) inv[mt2][h] = gma / lsum[mt2][h];

    #pragma unroll
    for (int mt2 = 0; mt2 < 2; mt2++) {
        const int rbase = nt + m0 + mt2 * 16 + g;
        #pragma unroll
        for (int n8 = 0; n8 < 16; n8++) {
            const int c0 = ch0 + n8 * 8 + 2 * t;
            size_t gi = ((size_t)b * C_IN + c0) * NPIX + rbase;
            out[gi]            = o[mt2][n8][0] * inv[mt2][0] + x[gi];
            out[gi + NPIX]     = o[mt2][n8][1] * inv[mt2][0] + x[gi + NPIX];
            out[gi + 8]        = o[mt2][n8][2] * inv[mt2][1] + x[gi + 8];
            out[gi + NPIX + 8] = o[mt2][n8][3] * inv[mt2][1] + x[gi + NPIX + 8];
        }
    }
}

// ---------------------------------------------------------------------------
extern "C" void kernel_launch(void* const* d_in, const int* in_sizes, int n_in,
                              void* d_out, int out_size)
{
    const float* x     = (const float*)d_in[0];
    const float* Wq    = (const float*)d_in[1];
    const float* bq    = (const float*)d_in[2];
    const float* Wk    = (const float*)d_in[3];
    const float* bk    = (const float*)d_in[4];
    const float* Wv    = (const float*)d_in[5];
    const float* bv    = (const float*)d_in[6];
    const float* gamma = (const float*)d_in[7];
    float* out = (float*)d_out;

    static bool attr_set = false;
    if (!attr_set) {
        cudaFuncSetAttribute(proj_qk_mma,
                             cudaFuncAttributeMaxDynamicSharedMemorySize, QK_SMEM);
        cudaFuncSetAttribute(proj_v_mma,
                             cudaFuncAttributeMaxDynamicSharedMemorySize, PV_SMEM);
        cudaFuncSetAttribute(attn_mma_kernel,
                             cudaFuncAttributeMaxDynamicSharedMemorySize, SMEM_ATTN);
        attr_set = true;
    }

    proj_qk_mma<<<dim3(NPIX / 128, 1, BATCH), 256, QK_SMEM>>>(x, Wq, bq, Wk, bk);
    proj_v_mma <<<dim3(NPIX / 128, 2, BATCH), 256, PV_SMEM>>>(x, Wv, bv);
    attn_mma_kernel<<<dim3(NPIX / MROWS, BATCH), 256, SMEM_ATTN>>>(x, gamma, out);
}